// round 7
// baseline (speedup 1.0000x reference)
#include <cuda_runtime.h>
#include <cuda_bf16.h>
#include <cstdint>
#include <cstddef>

#define NNODES 8192
#define DDIM   16
#define BATCH  4
#define NC     64                       // B*D output columns
#define MT     128                      // M tile
#define KT     32                       // K per stage
#define SPLITS 4
#define KRANGE (NNODES / SPLITS)        // 2048
#define NIT    (KRANGE / KT)            // 64
#define NMT    (NNODES / MT)            // 64
#define STAGES 4

#define NTENS  56                       // tensor-covered columns
#define NFFMA  8                        // FFMA-covered columns (56..63)

#define AROWF  40                       // A smem row: 32 fp32 + 8 pad (160B)
#define AROWB  160
#define XROWB  80                       // X bf16 smem row: 64B data + 16 pad
#define XFROWF 36                       // XF fp32 smem row: 32 + 4 pad (144B)
#define XFROWB 144
#define A_BYTES (MT * AROWB)            // 20480
#define X_BYTES (NC * XROWB)            // 5120
#define XF_BYTES (NFFMA * XFROWB)       // 1152
#define STAGE_BYTES (A_BYTES + X_BYTES + XF_BYTES)  // 26752
#define SMEM_TOTAL  (STAGES * STAGE_BYTES)          // 107008

__device__ __align__(128) __nv_bfloat16 g_XT[NC * NNODES];     // 1 MB bf16 (all cols)
__device__ __align__(128) float g_XTf[NFFMA * NNODES];         // 256 KB fp32 (cols 56..63)
__device__ __align__(128) float g_part[SPLITS * NNODES * NC];  // 8 MB

// ---- helpers ----
__device__ __forceinline__ uint32_t smem_u32(const void* p) {
    uint32_t a;
    asm("{ .reg .u64 t; cvta.to.shared.u64 t, %1; cvt.u32.u64 %0, t; }" : "=r"(a) : "l"(p));
    return a;
}
__device__ __forceinline__ void cp_async16(uint32_t smem_dst, const void* gmem_src) {
    asm volatile("cp.async.cg.shared.global [%0], [%1], 16;" :: "r"(smem_dst), "l"(gmem_src));
}
#define CP_COMMIT() asm volatile("cp.async.commit_group;" ::: "memory")

__device__ __forceinline__ uint32_t bf2(float lo, float hi) {
    __nv_bfloat162 v = __float22bfloat162_rn(make_float2(lo, hi));
    return *(uint32_t*)&v;
}

__device__ __forceinline__ void mma_bf16(float* c, const uint32_t* a, const uint32_t* b) {
    asm volatile(
        "mma.sync.aligned.m16n8k16.row.col.f32.bf16.bf16.f32 "
        "{%0,%1,%2,%3}, {%4,%5,%6,%7}, {%8,%9}, {%0,%1,%2,%3};"
        : "+f"(c[0]), "+f"(c[1]), "+f"(c[2]), "+f"(c[3])
        : "r"(a[0]), "r"(a[1]), "r"(a[2]), "r"(a[3]), "r"(b[0]), "r"(b[1]));
}

// ---------------- kernel 1: XT (bf16 all cols) + XTf (fp32 cols 56..63) ----------------
__global__ void __launch_bounds__(256) transpose_kernel(const float* __restrict__ h) {
    __shared__ float tile[16][66];
    int tid = threadIdx.x;
    int b  = blockIdx.x >> 7;
    int m0 = (blockIdx.x & 127) << 6;   // 64 rows per block
    const float* src = h + (size_t)b * (NNODES * DDIM) + (size_t)m0 * DDIM;
#pragma unroll
    for (int i = 0; i < 4; i++) {
        int j = i * 256 + tid;          // 1024 floats, coalesced
        tile[j & 15][j >> 4] = src[j];
    }
    __syncthreads();
#pragma unroll
    for (int i = 0; i < 2; i++) {
        int j = i * 256 + tid;          // 512 bf16x2 writes
        int d = j >> 5, mp = j & 31;
        float2 p = *(const float2*)&tile[d][2 * mp];
        __nv_bfloat162 v = __float22bfloat162_rn(p);
        *(__nv_bfloat162*)(g_XT + (size_t)(b * 16 + d) * NNODES + m0 + 2 * mp) = v;
    }
    if (b == 3) {                       // cols 56..63 = b3, d 8..15 -> fp32 copy
#pragma unroll
        for (int i = 0; i < 2; i++) {
            int j = i * 256 + tid;      // 512 = 8 cols x 64 rows
            int d = 8 + (j >> 6), m = j & 63;
            g_XTf[(size_t)(d - 8) * NNODES + m0 + m] = tile[d][m];
        }
    }
}

// ---------------- kernel 2: hybrid bf16-mma (cols 0..55) + fp32-FFMA (cols 56..63) ----------------
__global__ void __launch_bounds__(256, 2) gemm_kernel(const float* __restrict__ A) {
    extern __shared__ char smem[];
    uint32_t sb = smem_u32(smem);

    int tid   = threadIdx.x;
    int n0    = blockIdx.x * MT;
    int split = blockIdx.y;
    int kbase = split * KRANGE;

    int lane = tid & 31, wid = tid >> 5;
    int wm = wid & 3, wn = wid >> 2;
    int qrow = lane >> 2, qcol = lane & 3;

    // cp.async coords
    uint32_t offA[4]; size_t gofA[4];
#pragma unroll
    for (int i = 0; i < 4; i++) {
        int q = i * 256 + tid;                 // 1024 chunks: 128 rows x 8
        int row = q >> 3, c16 = q & 7;
        offA[i] = (uint32_t)(row * AROWB + c16 * 16);
        gofA[i] = (size_t)(n0 + row) * NNODES + (size_t)c16 * 4;   // fp32 elems
    }
    uint32_t offX; size_t gofX;
    {
        int row = tid >> 2, c16 = tid & 3;     // 256 chunks: 64 rows x 4
        offX = (uint32_t)(row * XROWB + c16 * 16);
        gofX = (size_t)row * NNODES + (size_t)c16 * 8;             // bf16 elems
    }
    bool doXF = tid < 64;
    uint32_t offXF = 0; size_t gofXF = 0;
    {
        int row = tid >> 3, c16 = tid & 7;     // 64 chunks: 8 cols x 8
        offXF = (uint32_t)(row * XFROWB + c16 * 16);
        gofXF = (size_t)row * NNODES + (size_t)c16 * 4;            // fp32 elems
    }

    // prologue
#pragma unroll
    for (int s = 0; s < STAGES - 1; s++) {
        int k0 = kbase + s * KT;
        uint32_t ab = sb + s * STAGE_BYTES;
#pragma unroll
        for (int i = 0; i < 4; i++) cp_async16(ab + offA[i], A + gofA[i] + k0);
        cp_async16(ab + A_BYTES + offX, g_XT + gofX + k0);
        if (doXF) cp_async16(ab + A_BYTES + X_BYTES + offXF, g_XTf + gofXF + k0);
        CP_COMMIT();
    }

    float acc[2][4][4];
#pragma unroll
    for (int mf = 0; mf < 2; mf++)
#pragma unroll
        for (int nf = 0; nf < 4; nf++)
#pragma unroll
            for (int r = 0; r < 4; r++) acc[mf][nf][r] = 0.0f;

    float f00 = 0.0f, f01 = 0.0f, f10 = 0.0f, f11 = 0.0f;  // FFMA accumulators
    const int frow0 = tid >> 2;            // rows frow0, frow0+64
    const int fcol  = tid & 3;             // XF rows fcol, fcol+4 (= cols 56+fcol, 60+fcol)

    const int arow0 = wm * 32 + qrow;
    const int xrow0 = wn * 32 + qrow;

    for (int it = 0; it < NIT; it++) {
        int slot = it & (STAGES - 1);
        asm volatile("cp.async.wait_group %0;" :: "n"(STAGES - 2) : "memory");
        __syncthreads();

        int nt = it + STAGES - 1;
        if (nt < NIT) {
            int k0 = kbase + nt * KT;
            uint32_t ab = sb + (nt & (STAGES - 1)) * STAGE_BYTES;
#pragma unroll
            for (int i = 0; i < 4; i++) cp_async16(ab + offA[i], A + gofA[i] + k0);
            cp_async16(ab + A_BYTES + offX, g_XT + gofX + k0);
            if (doXF) cp_async16(ab + A_BYTES + X_BYTES + offXF, g_XTf + gofXF + k0);
        }
        CP_COMMIT();

        const float* As = (const float*)(smem + slot * STAGE_BYTES);
        const char*  Xs = smem + slot * STAGE_BYTES + A_BYTES;
        const float* Xf = (const float*)(smem + slot * STAGE_BYTES + A_BYTES + X_BYTES);

        // ---- tensor part: cols wn*32 .. (+31 or +23) ----
#pragma unroll
        for (int kk = 0; kk < 2; kk++) {
            int kb = kk * 16;
            uint32_t a[2][4];
#pragma unroll
            for (int mf = 0; mf < 2; mf++) {
                int r = arow0 + mf * 16;
                float2 p0 = *(const float2*)(As + (size_t)r * AROWF + kb + 2 * qcol);
                float2 p1 = *(const float2*)(As + (size_t)(r + 8) * AROWF + kb + 2 * qcol);
                float2 p2 = *(const float2*)(As + (size_t)r * AROWF + kb + 2 * qcol + 8);
                float2 p3 = *(const float2*)(As + (size_t)(r + 8) * AROWF + kb + 2 * qcol + 8);
                a[mf][0] = bf2(p0.x, p0.y);
                a[mf][1] = bf2(p1.x, p1.y);
                a[mf][2] = bf2(p2.x, p2.y);
                a[mf][3] = bf2(p3.x, p3.y);
            }
            uint32_t b[4][2];
#pragma unroll
            for (int nf = 0; nf < 4; nf++) {
                if (wn == 1 && nf == 3) continue;
                int c = xrow0 + nf * 8;
                b[nf][0] = *(const uint32_t*)(Xs + c * XROWB + (kb + 2 * qcol) * 2);
                b[nf][1] = *(const uint32_t*)(Xs + c * XROWB + (kb + 2 * qcol) * 2 + 16);
            }
#pragma unroll
            for (int mf = 0; mf < 2; mf++)
#pragma unroll
                for (int nf = 0; nf < 4; nf++) {
                    if (wn == 1 && nf == 3) continue;
                    mma_bf16(acc[mf][nf], a[mf], b[nf]);
                }
        }

        // ---- FFMA part: exact fp32 for cols 56..63 ----
        {
            const float* a0p = As + (size_t)frow0 * AROWF;
            const float* a1p = As + (size_t)(frow0 + 64) * AROWF;
            const float* x0p = Xf + (size_t)fcol * XFROWF;
            const float* x1p = Xf + (size_t)(fcol + 4) * XFROWF;
#pragma unroll
            for (int i = 0; i < 8; i++) {
                float4 a0 = *(const float4*)(a0p + 4 * i);
                float4 a1 = *(const float4*)(a1p + 4 * i);
                float4 x0 = *(const float4*)(x0p + 4 * i);
                float4 x1 = *(const float4*)(x1p + 4 * i);
                f00 = fmaf(a0.x, x0.x, f00); f00 = fmaf(a0.y, x0.y, f00);
                f00 = fmaf(a0.z, x0.z, f00); f00 = fmaf(a0.w, x0.w, f00);
                f01 = fmaf(a0.x, x1.x, f01); f01 = fmaf(a0.y, x1.y, f01);
                f01 = fmaf(a0.z, x1.z, f01); f01 = fmaf(a0.w, x1.w, f01);
                f10 = fmaf(a1.x, x0.x, f10); f10 = fmaf(a1.y, x0.y, f10);
                f10 = fmaf(a1.z, x0.z, f10); f10 = fmaf(a1.w, x0.w, f10);
                f11 = fmaf(a1.x, x1.x, f11); f11 = fmaf(a1.y, x1.y, f11);
                f11 = fmaf(a1.z, x1.z, f11); f11 = fmaf(a1.w, x1.w, f11);
            }
        }
    }
    asm volatile("cp.async.wait_group 0;" ::: "memory");

    // epilogue: tensor cols
#pragma unroll
    for (int mf = 0; mf < 2; mf++)
#pragma unroll
        for (int nf = 0; nf < 4; nf++) {
            if (wn == 1 && nf == 3) continue;
            int m = n0 + wm * 32 + mf * 16 + qrow;
            int c = wn * 32 + nf * 8 + qcol * 2;
            float* p0 = g_part + ((size_t)split * NNODES + m) * NC + c;
            *(float2*)p0 = make_float2(acc[mf][nf][0], acc[mf][nf][1]);
            float* p1 = g_part + ((size_t)split * NNODES + m + 8) * NC + c;
            *(float2*)p1 = make_float2(acc[mf][nf][2], acc[mf][nf][3]);
        }
    // epilogue: FFMA cols
    {
        int m0r = n0 + frow0, m1r = n0 + frow0 + 64;
        int c0 = NTENS + fcol, c1 = NTENS + fcol + 4;
        g_part[((size_t)split * NNODES + m0r) * NC + c0] = f00;
        g_part[((size_t)split * NNODES + m0r) * NC + c1] = f01;
        g_part[((size_t)split * NNODES + m1r) * NC + c0] = f10;
        g_part[((size_t)split * NNODES + m1r) * NC + c1] = f11;
    }
}

// ---------------- kernel 3: fused MLPs ----------------
__global__ void __launch_bounds__(256) mlp_kernel(
    const float* __restrict__ h, const float* __restrict__ t,
    const float* __restrict__ W1f, const float* __restrict__ b1f,
    const float* __restrict__ W2f, const float* __restrict__ b2f,
    const float* __restrict__ W1g, const float* __restrict__ b1g,
    const float* __restrict__ W2g, const float* __restrict__ b2g,
    float* __restrict__ out) {
    __shared__ float sW1f[17 * 64], sW2f[64 * 16], sW1g[17 * 64], sW2g[64 * 16];
    __shared__ float sb1f[64], sb1g[64], sb2f[16], sb2g[16];
    int tid = threadIdx.x;
    for (int i = tid; i < 17 * 64; i += 256) { sW1f[i] = W1f[i]; sW1g[i] = W1g[i]; }
    for (int i = tid; i < 64 * 16; i += 256) { sW2f[i] = W2f[i]; sW2g[i] = W2g[i]; }
    if (tid < 64) { sb1f[tid] = b1f[tid]; sb1g[tid] = b1g[tid]; }
    if (tid < 16) { sb2f[tid] = b2f[tid]; sb2g[tid] = b2g[tid]; }
    __syncthreads();

    float tv = t[0];
    int gid = blockIdx.x * 256 + tid;
    int b = gid >> 13, n = gid & (NNODES - 1);

    float x[16], y[16];
    {
        size_t base = (size_t)n * NC + (size_t)b * DDIM;
        const float4* p0 = (const float4*)(g_part + base);
        const float4* p1 = (const float4*)(g_part + (size_t)1 * NNODES * NC + base);
        const float4* p2 = (const float4*)(g_part + (size_t)2 * NNODES * NC + base);
        const float4* p3 = (const float4*)(g_part + (size_t)3 * NNODES * NC + base);
#pragma unroll
        for (int k = 0; k < 4; k++) {
            float4 a = p0[k], bb = p1[k], c = p2[k], d = p3[k];
            x[4 * k + 0] = a.x + bb.x + c.x + d.x;
            x[4 * k + 1] = a.y + bb.y + c.y + d.y;
            x[4 * k + 2] = a.z + bb.z + c.z + d.z;
            x[4 * k + 3] = a.w + bb.w + c.w + d.w;
        }
        const float4* ph = (const float4*)(h + (size_t)b * NNODES * DDIM + (size_t)n * DDIM);
#pragma unroll
        for (int k = 0; k < 4; k++) {
            float4 a = ph[k];
            y[4 * k + 0] = a.x; y[4 * k + 1] = a.y; y[4 * k + 2] = a.z; y[4 * k + 3] = a.w;
        }
    }

    float drift[16], dacc[16];
#pragma unroll
    for (int d = 0; d < 16; d++) { drift[d] = sb2f[d]; dacc[d] = sb2g[d]; }

    for (int j = 0; j < 64; j++) {
        float zf = sb1f[j] + tv * sW1f[16 * 64 + j];
        float zg = sb1g[j] + tv * sW1g[16 * 64 + j];
#pragma unroll
        for (int i = 0; i < 16; i++) {
            zf = fmaf(x[i], sW1f[i * 64 + j], zf);
            zg = fmaf(y[i], sW1g[i * 64 + j], zg);
        }
        float af = 1.0f - 2.0f / (__expf(2.0f * zf) + 1.0f);   // tanh via MUFU exp
        float ag = 1.0f / (1.0f + __expf(-zg));
#pragma unroll
        for (int d = 0; d < 16; d++) {
            drift[d] = fmaf(af, sW2f[j * 16 + d], drift[d]);
            dacc[d]  = fmaf(ag, sW2g[j * 16 + d], dacc[d]);
        }
    }

    size_t o0 = (size_t)b * NNODES * DDIM + (size_t)n * DDIM;
    float4* od = (float4*)(out + o0);
    float4* og = (float4*)(out + (size_t)BATCH * NNODES * DDIM + o0);
#pragma unroll
    for (int k = 0; k < 4; k++) {
        od[k] = make_float4(drift[4 * k], drift[4 * k + 1], drift[4 * k + 2], drift[4 * k + 3]);
        float g0 = 0.1f / (1.0f + __expf(-dacc[4 * k + 0]));
        float g1 = 0.1f / (1.0f + __expf(-dacc[4 * k + 1]));
        float g2 = 0.1f / (1.0f + __expf(-dacc[4 * k + 2]));
        float g3 = 0.1f / (1.0f + __expf(-dacc[4 * k + 3]));
        og[k] = make_float4(g0, g1, g2, g3);
    }
}

extern "C" void kernel_launch(void* const* d_in, const int* in_sizes, int n_in,
                              void* d_out, int out_size) {
    (void)in_sizes; (void)n_in; (void)out_size;
    const float* h   = (const float*)d_in[0];
    const float* t   = (const float*)d_in[1];
    const float* A   = (const float*)d_in[2];
    const float* W1f = (const float*)d_in[3];
    const float* b1f = (const float*)d_in[4];
    const float* W2f = (const float*)d_in[5];
    const float* b2f = (const float*)d_in[6];
    const float* W1g = (const float*)d_in[7];
    const float* b1g = (const float*)d_in[8];
    const float* W2g = (const float*)d_in[9];
    const float* b2g = (const float*)d_in[10];
    float* out = (float*)d_out;

    cudaFuncSetAttribute(gemm_kernel, cudaFuncAttributeMaxDynamicSharedMemorySize, SMEM_TOTAL);

    transpose_kernel<<<512, 256>>>(h);
    gemm_kernel<<<dim3(NMT, SPLITS), 256, SMEM_TOTAL>>>(A);
    mlp_kernel<<<128, 256>>>(h, t, W1f, b1f, W2f, b2f, W1g, b1g, W2g, b2g, out);
}

// round 8
// speedup vs baseline: 1.5456x; 1.5456x over previous
#include <cuda_runtime.h>
#include <cuda_bf16.h>
#include <cstdint>
#include <cstddef>

#define NNODES 8192
#define DDIM   16
#define BATCH  4
#define NC     64                       // B*D output columns
#define MT     128                      // M tile
#define KT     32                       // K per stage
#define NKU    256                      // k-units per m-tile (8192/32)
#define NMT    64                       // m-tiles
#define GTOT   (NMT * NKU)              // 16384 global work units
#define NCTA   296                      // 148 SMs x 2 CTAs, exact fit
#define SLOTS  6                        // max k-segments per m-tile
#define STAGES 4

#define AROWF  40                       // A smem row: 32 fp32 + 8 pad (160B)
#define AROWB  160
#define XROWB  80                       // X smem row: 64B bf16 + 16 pad
#define A_BYTES (MT * AROWB)            // 20480
#define X_BYTES (NC * XROWB)            // 5120
#define STAGE_BYTES (A_BYTES + X_BYTES) // 25600
#define SMEM_TOTAL  (STAGES * STAGE_BYTES) // 102400

__device__ __align__(128) __nv_bfloat16 g_XT[NC * NNODES];     // 1 MB bf16
__device__ __align__(128) float g_part[SLOTS * NNODES * NC];   // 12.6 MB

// CTA c covers global units [s(c), s(c+1)), s(c) = floor(2048*c/37)
__device__ __forceinline__ int sched_start(int c) { return (c * 2048) / 37; }
// first CTA touching m-tile m
__device__ __forceinline__ int sched_cfirst(int m) { return ((9472 * m + 2084) >> 11) - 1; }
// last CTA touching m-tile m
__device__ __forceinline__ int sched_clast(int m) { return ((37 * (m + 1) + 7) >> 3) - 1; }

// ---- helpers ----
__device__ __forceinline__ uint32_t smem_u32(const void* p) {
    uint32_t a;
    asm("{ .reg .u64 t; cvta.to.shared.u64 t, %1; cvt.u32.u64 %0, t; }" : "=r"(a) : "l"(p));
    return a;
}
__device__ __forceinline__ void cp_async16(uint32_t smem_dst, const void* gmem_src) {
    asm volatile("cp.async.cg.shared.global [%0], [%1], 16;" :: "r"(smem_dst), "l"(gmem_src));
}
#define CP_COMMIT() asm volatile("cp.async.commit_group;" ::: "memory")

__device__ __forceinline__ uint32_t bf2(float lo, float hi) {
    __nv_bfloat162 v = __float22bfloat162_rn(make_float2(lo, hi));
    return *(uint32_t*)&v;
}

__device__ __forceinline__ void mma_bf16(float* c, const uint32_t* a, const uint32_t* b) {
    asm volatile(
        "mma.sync.aligned.m16n8k16.row.col.f32.bf16.bf16.f32 "
        "{%0,%1,%2,%3}, {%4,%5,%6,%7}, {%8,%9}, {%0,%1,%2,%3};"
        : "+f"(c[0]), "+f"(c[1]), "+f"(c[2]), "+f"(c[3])
        : "r"(a[0]), "r"(a[1]), "r"(a[2]), "r"(a[3]), "r"(b[0]), "r"(b[1]));
}

// ---------------- kernel 1: XT[b*16+d][m] = bf16(h[b][m*16+d]) ----------------
__global__ void __launch_bounds__(256) transpose_kernel(const float* __restrict__ h) {
    __shared__ float tile[16][66];
    int tid = threadIdx.x;
    int b  = blockIdx.x >> 7;
    int m0 = (blockIdx.x & 127) << 6;   // 64 rows per block
    const float* src = h + (size_t)b * (NNODES * DDIM) + (size_t)m0 * DDIM;
#pragma unroll
    for (int i = 0; i < 4; i++) {
        int j = i * 256 + tid;          // 1024 floats, coalesced
        tile[j & 15][j >> 4] = src[j];
    }
    __syncthreads();
#pragma unroll
    for (int i = 0; i < 2; i++) {
        int j = i * 256 + tid;          // 512 bf16x2 writes
        int d = j >> 5, mp = j & 31;
        float2 p = *(const float2*)&tile[d][2 * mp];
        __nv_bfloat162 v = __float22bfloat162_rn(p);
        *(__nv_bfloat162*)(g_XT + (size_t)(b * 16 + d) * NNODES + m0 + 2 * mp) = v;
    }
}

// ---------------- kernel 2: balanced bf16 mma GEMM -> g_part ----------------
// 296 CTAs, each a contiguous range of (m-tile, k-chunk) units; flush per segment.
__global__ void __launch_bounds__(256, 2) gemm_kernel(const float* __restrict__ A) {
    extern __shared__ char smem[];
    uint32_t sb = smem_u32(smem);

    int tid = threadIdx.x;
    int c   = blockIdx.x;
    int gs  = sched_start(c);
    int ge  = sched_start(c + 1);

    int lane = tid & 31, wid = tid >> 5;
    int wm = wid & 3, wn = wid >> 2;
    int qrow = lane >> 2, qcol = lane & 3;

    // per-thread static cp.async coords (m/k-independent parts)
    uint32_t offA[4]; size_t aoffA[4];
#pragma unroll
    for (int i = 0; i < 4; i++) {
        int q = i * 256 + tid;                 // 1024 chunks: 128 rows x 8
        int row = q >> 3, c16 = q & 7;
        offA[i] = (uint32_t)(row * AROWB + c16 * 16);
        aoffA[i] = (size_t)row * NNODES + (size_t)c16 * 4;   // fp32 elems
    }
    uint32_t offX; size_t xoff;
    {
        int row = tid >> 2, c16 = tid & 3;     // 256 chunks: 64 rows x 4
        offX = (uint32_t)(row * XROWB + c16 * 16);
        xoff = (size_t)row * NNODES + (size_t)c16 * 8;       // bf16 elems
    }

    // prologue: prefetch units gs..gs+2 into stages (g&3)
#pragma unroll
    for (int p = 0; p < STAGES - 1; p++) {
        int g = gs + p;                        // range >= 55, always valid
        int m = g >> 8, k0 = (g & 255) * KT;
        size_t abase = (size_t)m * MT * NNODES + k0;
        uint32_t ab = sb + (g & 3) * STAGE_BYTES;
#pragma unroll
        for (int i = 0; i < 4; i++) cp_async16(ab + offA[i], A + abase + aoffA[i]);
        cp_async16(ab + A_BYTES + offX, g_XT + xoff + k0);
        CP_COMMIT();
    }

    float acc[2][4][4];
#pragma unroll
    for (int mf = 0; mf < 2; mf++)
#pragma unroll
        for (int nf = 0; nf < 4; nf++)
#pragma unroll
            for (int r = 0; r < 4; r++) acc[mf][nf][r] = 0.0f;

    const int arow0 = wm * 32 + qrow;
    const int xrow0 = wn * 32 + qrow;
    int cur_m = gs >> 8;

    for (int g = gs; g < ge; g++) {
        asm volatile("cp.async.wait_group %0;" :: "n"(STAGES - 2) : "memory");
        __syncthreads();

        int gn = g + STAGES - 1;
        if (gn < ge) {
            int m = gn >> 8, k0 = (gn & 255) * KT;
            size_t abase = (size_t)m * MT * NNODES + k0;
            uint32_t ab = sb + (gn & 3) * STAGE_BYTES;
#pragma unroll
            for (int i = 0; i < 4; i++) cp_async16(ab + offA[i], A + abase + aoffA[i]);
            cp_async16(ab + A_BYTES + offX, g_XT + xoff + k0);
        }
        CP_COMMIT();

        const float* As = (const float*)(smem + (g & 3) * STAGE_BYTES);
        const char*  Xs = smem + (g & 3) * STAGE_BYTES + A_BYTES;
#pragma unroll
        for (int kk = 0; kk < 2; kk++) {
            int kb = kk * 16;
            uint32_t a[2][4];
#pragma unroll
            for (int mf = 0; mf < 2; mf++) {
                int r = arow0 + mf * 16;
                float2 p0 = *(const float2*)(As + (size_t)r * AROWF + kb + 2 * qcol);
                float2 p1 = *(const float2*)(As + (size_t)(r + 8) * AROWF + kb + 2 * qcol);
                float2 p2 = *(const float2*)(As + (size_t)r * AROWF + kb + 2 * qcol + 8);
                float2 p3 = *(const float2*)(As + (size_t)(r + 8) * AROWF + kb + 2 * qcol + 8);
                a[mf][0] = bf2(p0.x, p0.y);
                a[mf][1] = bf2(p1.x, p1.y);
                a[mf][2] = bf2(p2.x, p2.y);
                a[mf][3] = bf2(p3.x, p3.y);
            }
            uint32_t b[4][2];
#pragma unroll
            for (int nf = 0; nf < 4; nf++) {
                int cc = xrow0 + nf * 8;
                b[nf][0] = *(const uint32_t*)(Xs + cc * XROWB + (kb + 2 * qcol) * 2);
                b[nf][1] = *(const uint32_t*)(Xs + cc * XROWB + (kb + 2 * qcol) * 2 + 16);
            }
#pragma unroll
            for (int mf = 0; mf < 2; mf++)
#pragma unroll
                for (int nf = 0; nf < 4; nf++)
                    mma_bf16(acc[mf][nf], a[mf], b[nf]);
        }

        // segment end: m-tile boundary or end of range -> flush partials
        if ((g & 255) == 255 || g == ge - 1) {
            int slot = c - sched_cfirst(cur_m);
            int n0 = cur_m * MT;
#pragma unroll
            for (int mf = 0; mf < 2; mf++)
#pragma unroll
                for (int nf = 0; nf < 4; nf++) {
                    int m = n0 + wm * 32 + mf * 16 + qrow;
                    int cc = wn * 32 + nf * 8 + qcol * 2;
                    float* p0 = g_part + ((size_t)slot * NNODES + m) * NC + cc;
                    *(float2*)p0 = make_float2(acc[mf][nf][0], acc[mf][nf][1]);
                    float* p1 = g_part + ((size_t)slot * NNODES + m + 8) * NC + cc;
                    *(float2*)p1 = make_float2(acc[mf][nf][2], acc[mf][nf][3]);
                    acc[mf][nf][0] = 0.0f; acc[mf][nf][1] = 0.0f;
                    acc[mf][nf][2] = 0.0f; acc[mf][nf][3] = 0.0f;
                }
            cur_m++;
        }
    }
    asm volatile("cp.async.wait_group 0;" ::: "memory");
}

// ---------------- kernel 3: fused MLPs (sums variable k-segments) ----------------
__global__ void __launch_bounds__(256) mlp_kernel(
    const float* __restrict__ h, const float* __restrict__ t,
    const float* __restrict__ W1f, const float* __restrict__ b1f,
    const float* __restrict__ W2f, const float* __restrict__ b2f,
    const float* __restrict__ W1g, const float* __restrict__ b1g,
    const float* __restrict__ W2g, const float* __restrict__ b2g,
    float* __restrict__ out) {
    __shared__ float sW1f[17 * 64], sW2f[64 * 16], sW1g[17 * 64], sW2g[64 * 16];
    __shared__ float sb1f[64], sb1g[64], sb2f[16], sb2g[16];
    int tid = threadIdx.x;
    for (int i = tid; i < 17 * 64; i += 256) { sW1f[i] = W1f[i]; sW1g[i] = W1g[i]; }
    for (int i = tid; i < 64 * 16; i += 256) { sW2f[i] = W2f[i]; sW2g[i] = W2g[i]; }
    if (tid < 64) { sb1f[tid] = b1f[tid]; sb1g[tid] = b1g[tid]; }
    if (tid < 16) { sb2f[tid] = b2f[tid]; sb2g[tid] = b2g[tid]; }
    __syncthreads();

    float tv = t[0];
    int gid = blockIdx.x * 256 + tid;
    int b = gid >> 13, n = gid & (NNODES - 1);

    // number of k-segments for this node's m-tile
    int mt = n >> 7;
    int nseg = sched_clast(mt) - sched_cfirst(mt) + 1;   // 5 or 6

    float x[16], y[16];
    {
        size_t base = (size_t)n * NC + (size_t)b * DDIM;
#pragma unroll
        for (int k = 0; k < 4; k++) {
            x[4 * k + 0] = 0.0f; x[4 * k + 1] = 0.0f;
            x[4 * k + 2] = 0.0f; x[4 * k + 3] = 0.0f;
        }
        for (int s = 0; s < nseg; s++) {
            const float4* p = (const float4*)(g_part + (size_t)s * NNODES * NC + base);
#pragma unroll
            for (int k = 0; k < 4; k++) {
                float4 a = p[k];
                x[4 * k + 0] += a.x; x[4 * k + 1] += a.y;
                x[4 * k + 2] += a.z; x[4 * k + 3] += a.w;
            }
        }
        const float4* ph = (const float4*)(h + (size_t)b * NNODES * DDIM + (size_t)n * DDIM);
#pragma unroll
        for (int k = 0; k < 4; k++) {
            float4 a = ph[k];
            y[4 * k + 0] = a.x; y[4 * k + 1] = a.y; y[4 * k + 2] = a.z; y[4 * k + 3] = a.w;
        }
    }

    float drift[16], dacc[16];
#pragma unroll
    for (int d = 0; d < 16; d++) { drift[d] = sb2f[d]; dacc[d] = sb2g[d]; }

    for (int j = 0; j < 64; j++) {
        float zf = sb1f[j] + tv * sW1f[16 * 64 + j];
        float zg = sb1g[j] + tv * sW1g[16 * 64 + j];
#pragma unroll
        for (int i = 0; i < 16; i++) {
            zf = fmaf(x[i], sW1f[i * 64 + j], zf);
            zg = fmaf(y[i], sW1g[i * 64 + j], zg);
        }
        float af = 1.0f - 2.0f / (__expf(2.0f * zf) + 1.0f);   // tanh via MUFU exp
        float ag = 1.0f / (1.0f + __expf(-zg));
#pragma unroll
        for (int d = 0; d < 16; d++) {
            drift[d] = fmaf(af, sW2f[j * 16 + d], drift[d]);
            dacc[d]  = fmaf(ag, sW2g[j * 16 + d], dacc[d]);
        }
    }

    size_t o0 = (size_t)b * NNODES * DDIM + (size_t)n * DDIM;
    float4* od = (float4*)(out + o0);
    float4* og = (float4*)(out + (size_t)BATCH * NNODES * DDIM + o0);
#pragma unroll
    for (int k = 0; k < 4; k++) {
        od[k] = make_float4(drift[4 * k], drift[4 * k + 1], drift[4 * k + 2], drift[4 * k + 3]);
        float g0 = 0.1f / (1.0f + __expf(-dacc[4 * k + 0]));
        float g1 = 0.1f / (1.0f + __expf(-dacc[4 * k + 1]));
        float g2 = 0.1f / (1.0f + __expf(-dacc[4 * k + 2]));
        float g3 = 0.1f / (1.0f + __expf(-dacc[4 * k + 3]));
        og[k] = make_float4(g0, g1, g2, g3);
    }
}

extern "C" void kernel_launch(void* const* d_in, const int* in_sizes, int n_in,
                              void* d_out, int out_size) {
    (void)in_sizes; (void)n_in; (void)out_size;
    const float* h   = (const float*)d_in[0];
    const float* t   = (const float*)d_in[1];
    const float* A   = (const float*)d_in[2];
    const float* W1f = (const float*)d_in[3];
    const float* b1f = (const float*)d_in[4];
    const float* W2f = (const float*)d_in[5];
    const float* b2f = (const float*)d_in[6];
    const float* W1g = (const float*)d_in[7];
    const float* b1g = (const float*)d_in[8];
    const float* W2g = (const float*)d_in[9];
    const float* b2g = (const float*)d_in[10];
    float* out = (float*)d_out;

    cudaFuncSetAttribute(gemm_kernel, cudaFuncAttributeMaxDynamicSharedMemorySize, SMEM_TOTAL);

    transpose_kernel<<<512, 256>>>(h);
    gemm_kernel<<<NCTA, 256, SMEM_TOTAL>>>(A);
    mlp_kernel<<<128, 256>>>(h, t, W1f, b1f, W2f, b2f, W1g, b1g, W2g, b2g, out);
}